// round 16
// baseline (speedup 1.0000x reference)
#include <cuda_runtime.h>

#define ADAM_B1 0.9f
#define ADAM_B2 0.999f
#define ADAM_LR 0.02f
#define LOG2E_F 1.4426950408889634f
#define LN2_F   0.6931471805599453f
#define PXT 3   // pixels per thread

__device__ __forceinline__ float rcp_a(float x) {
    float r; asm("rcp.approx.f32 %0, %1;" : "=f"(r) : "f"(x)); return r;
}
__device__ __forceinline__ float rsq_a(float x) {
    float r; asm("rsqrt.approx.f32 %0, %1;" : "=f"(r) : "f"(x)); return r;
}
__device__ __forceinline__ float sqrt_a(float x) {
    float r; asm("sqrt.approx.f32 %0, %1;" : "=f"(r) : "f"(x)); return r;
}
__device__ __forceinline__ float ex2_a(float x) {
    float r; asm("ex2.approx.f32 %0, %1;" : "=f"(r) : "f"(x)); return r;
}
#define EXPA(x) ex2_a(LOG2E_F * (x))

// ---------------- main kernel: 3 pixels per thread, PURE SCALAR ----------------
__global__ __launch_bounds__(32)
void pe_kernel(const float* __restrict__ X,     // (B,5,5)
               const float* __restrict__ Yg,    // (B,5)
               const float* __restrict__ ch0g,  // (B,1,3)
               const float* __restrict__ pf,    // (14,)
               const float* __restrict__ xag,   // (3,)
               const float* __restrict__ Sag,   // (3,3)
               const float* __restrict__ Seg,   // (5,5)
               const int*   __restrict__ nitp,
               float* __restrict__ out,         // (B,9)
               int B)
{
    int tIdx = blockIdx.x * blockDim.x + threadIdx.x;
    int base = PXT * tIdx;
    if (base >= B) return;
    int px[PXT];
    #pragma unroll
    for (int s = 0; s < PXT; s++) px[s] = min(base + s, B - 1);

    const float L[5] = {-0.275f, 0.025f, 0.5f, 0.70f, 1.15f};

    // ---- uniform (broadcast) parameters ----
    float p0=pf[0], p1=pf[1], p2=pf[2], p3=pf[3], p4=pf[4], p5=pf[5], p6=pf[6];
    const float cna = pf[12] * 0.005f;
    const float cnb = pf[13] * 0.005f;
    const float c7s = pf[7] * 0.089f;
    const float c8s = pf[8] * 0.1245f;
    const float cnab = cna + cnb;

    // per-lambda folded constants
    float ABl[5], ACDl[5], BBSl[5];
    #pragma unroll
    for (int l = 0; l < 5; l++) {
        float aph = p0 * 0.05f * (1.0f + p1 * 0.1f * L[l] + p2 * 0.01f);
        float acd = p5 * 0.1f * expf(-p6 * 1.7f * L[l]);
        float bbs = p3 * 0.001f * (1.0f + p4 * 0.05f * L[l]);
        ABl[l]  = aph + bbs;
        ACDl[l] = acd;
        BBSl[l] = bbs;
    }

    // diagonality of symmetrized matrices
    bool diag = ((Seg[0*5+1]+Seg[1*5+0])==0.f && (Seg[0*5+2]+Seg[2*5+0])==0.f &&
                 (Seg[0*5+3]+Seg[3*5+0])==0.f && (Seg[0*5+4]+Seg[4*5+0])==0.f &&
                 (Seg[1*5+2]+Seg[2*5+1])==0.f && (Seg[1*5+3]+Seg[3*5+1])==0.f &&
                 (Seg[1*5+4]+Seg[4*5+1])==0.f && (Seg[2*5+3]+Seg[3*5+2])==0.f &&
                 (Seg[2*5+4]+Seg[4*5+2])==0.f && (Seg[3*5+4]+Seg[4*5+3])==0.f &&
                 (Sag[0*3+1]+Sag[1*3+0])==0.f && (Sag[0*3+2]+Sag[2*3+0])==0.f &&
                 (Sag[1*3+2]+Sag[2*3+1])==0.f);

    int iters = 50;
    if (nitp) {
        int it = *nitp;
        if (it >= 1 && it <= 100000000) iters = it;
        else {
            float f = __int_as_float(it);
            if (f >= 1.0f && f <= 1e8f) iters = (int)f;
        }
    }

    float b1t = 1.0f, b2t = 1.0f;
    float chla_f[PXT], nap_f[PXT], cdom_f[PXT], ch0_out[PXT];

    if (diag) {
        // ===== scalar fused diagonal path, log2-domain, PXT independent chains =====
        float fe2[PXT][5], yfn[PXT][5];
        #pragma unroll
        for (int s = 0; s < PXT; s++) {
            int b = px[s];
            #pragma unroll
            for (int l = 0; l < 5; l++) {
                float e0 = X[b*25 + l*5 + 0], e1 = X[b*25 + l*5 + 1];
                float fe = __fdividef(e0 + 0.5f*e1, e0 + e1);
                fe2[s][l] = Seg[l*5+l] * fe * fe;
                yfn[s][l] = -__fdividef(Yg[b*5 + l], fe);
            }
        }
        const float sa0l2 = Sag[0]*LN2_F, sa1l2 = Sag[4]*LN2_F, sa2l2 = Sag[8]*LN2_F;
        const float bp0 = -Sag[0]*xag[0], bp1 = -Sag[4]*xag[1], bp2 = -Sag[8]*xag[2];

        float cl[PXT][3], m[PXT][3], v[PXT][3];
        #pragma unroll
        for (int s = 0; s < PXT; s++)
            #pragma unroll
            for (int k = 0; k < 3; k++) {
                cl[s][k] = ch0g[px[s]*3 + k] * LOG2E_F;
                m[s][k] = 0.0f;
                v[s][k] = 1e-30f;
            }

        for (int t = 0; t < iters; t++) {
            b1t *= ADAM_B1; b2t *= ADAM_B2;
            float nlrt = (-ADAM_LR * LOG2E_F) * sqrt_a(1.0f - b2t) * rcp_a(1.0f - b1t);

            #pragma unroll
            for (int s = 0; s < PXT; s++) {
                float chla = ex2_a(cl[s][0]);
                float nap  = ex2_a(cl[s][1]);
                float cdom = ex2_a(cl[s][2]);

                float NC = fmaf(cnab, nap, 0.0057f);
                float DB = fmaf(cnb,  nap, 0.0012f);

                float acc0 = 0.f, T = 0.f, acc2 = 0.f;
                #pragma unroll
                for (int l = 0; l < 5; l++) {
                    float sv = fmaf(ABl[l], chla, fmaf(ACDl[l], cdom, NC)); // a+bb
                    float bb = fmaf(BBSl[l], chla, DB);
                    float iv = rcp_a(sv);
                    float u  = bb * iv;
                    float t1 = fmaf(c8s, u, c7s);
                    float pv = fmaf(t1, u, yfn[s][l]);        // rrs/FE - Y/FE
                    float dv = fmaf(c8s, u, t1);              // c7 + 2 c8 u
                    float q  = (fe2[s][l] * iv) * (pv * dv);
                    float qu = q * u;
                    float tg = fmaf(-u, ABl[l], BBSl[l]);     // BBS - u*(Aph+Bbs)
                    float tT = fmaf(-u, cnab, cnb);           // cnb - u*cnab
                    acc0 = fmaf(q, tg, acc0);
                    T    = fmaf(q, tT, T);
                    acc2 = fmaf(qu, -ACDl[l], acc2);
                }

                float g0 = fmaf(acc0, chla, fmaf(sa0l2, cl[s][0], bp0));
                float g1 = fmaf(T,    nap,  fmaf(sa1l2, cl[s][1], bp1));
                float g2 = fmaf(acc2, cdom, fmaf(sa2l2, cl[s][2], bp2));

                float g[3] = { g0, g1, g2 };
                #pragma unroll
                for (int k = 0; k < 3; k++) {
                    m[s][k] = fmaf(g[k], 1.0f - ADAM_B1, m[s][k] * ADAM_B1);
                    v[s][k] = fmaf(g[k] * g[k], 1.0f - ADAM_B2, v[s][k] * ADAM_B2);
                    cl[s][k] = fmaf(m[s][k] * rsq_a(v[s][k]), nlrt, cl[s][k]);
                }
            }
        }
        #pragma unroll
        for (int s = 0; s < PXT; s++) {
            ch0_out[s] = cl[s][0] * LN2_F;
            chla_f[s] = ex2_a(cl[s][0]);
            nap_f[s]  = ex2_a(cl[s][1]);
            cdom_f[s] = ex2_a(cl[s][2]);
        }
    } else {
        // ===== general scalar two-pass fallback (dense Se, Sa) =====
        float Se[5][5];
        #pragma unroll
        for (int i = 0; i < 5; i++)
            #pragma unroll
            for (int j = 0; j < 5; j++)
                Se[i][j] = 0.5f * (Seg[i*5 + j] + Seg[j*5 + i]);
        float SaS[3][3];
        #pragma unroll
        for (int i = 0; i < 3; i++)
            #pragma unroll
            for (int j = 0; j < 3; j++)
                SaS[i][j] = 0.5f * (Sag[i*3 + j] + Sag[j*3 + i]);
        float xa0 = xag[0], xa1 = xag[1], xa2 = xag[2];
        float bp0 = -(SaS[0][0]*xa0 + SaS[0][1]*xa1 + SaS[0][2]*xa2);
        float bp1 = -(SaS[1][0]*xa0 + SaS[1][1]*xa1 + SaS[1][2]*xa2);
        float bp2 = -(SaS[2][0]*xa0 + SaS[2][1]*xa1 + SaS[2][2]*xa2);

        float fe[PXT][5], yv[PXT][5];
        #pragma unroll
        for (int s = 0; s < PXT; s++) {
            int b = px[s];
            #pragma unroll
            for (int l = 0; l < 5; l++) {
                float e0 = X[b*25 + l*5 + 0], e1 = X[b*25 + l*5 + 1];
                fe[s][l] = __fdividef(e0 + 0.5f*e1, e0 + e1);
                yv[s][l] = Yg[b*5 + l];
            }
        }

        float ch[PXT][3], m[PXT][3], v[PXT][3];
        #pragma unroll
        for (int s = 0; s < PXT; s++)
            #pragma unroll
            for (int k = 0; k < 3; k++) {
                ch[s][k] = ch0g[px[s]*3 + k];
                m[s][k] = 0.0f;
                v[s][k] = 1e-30f;
            }

        for (int t = 0; t < iters; t++) {
            b1t *= ADAM_B1; b2t *= ADAM_B2;
            float nlrt = -ADAM_LR * sqrt_a(1.0f - b2t) * rcp_a(1.0f - b1t);

            #pragma unroll
            for (int s = 0; s < PXT; s++) {
                float chla = EXPA(ch[s][0]);
                float nap  = EXPA(ch[s][1]);
                float cdom = EXPA(ch[s][2]);

                float da1  = cna * nap;
                float dbb1 = cnb * nap;

                float r[5], u[5], iv[5];
                #pragma unroll
                for (int l = 0; l < 5; l++) {
                    float aph = ABl[l] - BBSl[l];
                    float a  = 0.0045f + aph*chla + ACDl[l]*cdom + da1;
                    float bb = 0.0012f + BBSl[l]*chla + dbb1;
                    iv[l] = rcp_a(a + bb);
                    u[l]  = bb * iv[l];
                    float rrs = fmaf(c8s, u[l], c7s) * u[l] * fe[s][l];
                    r[l] = rrs - yv[s][l];
                }

                float g0 = fmaf(SaS[0][0], ch[s][0], fmaf(SaS[0][1], ch[s][1], fmaf(SaS[0][2], ch[s][2], bp0)));
                float g1 = fmaf(SaS[1][0], ch[s][0], fmaf(SaS[1][1], ch[s][1], fmaf(SaS[1][2], ch[s][2], bp1)));
                float g2 = fmaf(SaS[2][0], ch[s][0], fmaf(SaS[2][1], ch[s][1], fmaf(SaS[2][2], ch[s][2], bp2)));

                #pragma unroll
                for (int l = 0; l < 5; l++) {
                    float w = fmaf(Se[l][0], r[0], fmaf(Se[l][1], r[1],
                              fmaf(Se[l][2], r[2], fmaf(Se[l][3], r[3], Se[l][4]*r[4]))));
                    float dg = fmaf(2.0f*c8s, u[l], c7s) * fe[s][l];
                    float q  = w * dg * iv[l];
                    float ul = u[l], om = 1.0f - ul;
                    float aph = ABl[l] - BBSl[l];
                    float da0 = aph*chla, dbb0 = BBSl[l]*chla;
                    float da2 = ACDl[l]*cdom;
                    g0 += q * (om * dbb0 - ul * da0);
                    g1 += q * (om * dbb1 - ul * da1);
                    g2 -= q * ul * da2;
                }

                float g[3] = { g0, g1, g2 };
                #pragma unroll
                for (int k = 0; k < 3; k++) {
                    m[s][k] = fmaf(g[k], 1.0f - ADAM_B1, m[s][k] * ADAM_B1);
                    v[s][k] = fmaf(g[k] * g[k], 1.0f - ADAM_B2, v[s][k] * ADAM_B2);
                    ch[s][k] = fmaf(m[s][k] * rsq_a(v[s][k]), nlrt, ch[s][k]);
                }
            }
        }
        #pragma unroll
        for (int s = 0; s < PXT; s++) {
            ch0_out[s] = ch[s][0];
            chla_f[s] = EXPA(ch[s][0]);
            nap_f[s]  = EXPA(ch[s][1]);
            cdom_f[s] = EXPA(ch[s][2]);
        }
    }

    // ---- outputs: [ch0, kd(5), bbp(3)] — reuses loop constants ----
    {
        float kfac = pf[9] * 0.9f + pf[10] * 0.1f;
        float p11v = pf[11];
        const int J[3] = {1, 2, 4};

        #pragma unroll
        for (int s = 0; s < PXT; s++) {
            int b = px[s];
            float NCo = fmaf(cnab, nap_f[s], 0.0057f);
            float c2n = cnb * nap_f[s];

            out[b*9 + 0] = ch0_out[s];
            #pragma unroll
            for (int l = 0; l < 5; l++) {
                float ab = fmaf(ABl[l], chla_f[s], fmaf(ACDl[l], cdom_f[s], NCo));  // a+bb
                float x3 = X[b*25 + l*5 + 3];
                float mu = 0.5f + 0.5f * rcp_a(1.0f + EXPA(-x3));
                out[b*9 + 1 + l] = ab * kfac * rcp_a(mu);
            }
            #pragma unroll
            for (int j = 0; j < 3; j++) {
                out[b*9 + 6 + j] = p11v * fmaf(BBSl[J[j]], chla_f[s], c2n);
            }
        }
    }
}

extern "C" void kernel_launch(void* const* d_in, const int* in_sizes, int n_in,
                              void* d_out, int out_size) {
    const float* X    = (const float*)d_in[0];
    const float* Y    = (const float*)d_in[1];
    const float* ch0  = (const float*)d_in[2];
    const float* pf   = (const float*)d_in[3];
    const float* xa   = (const float*)d_in[4];
    const float* Sa   = (const float*)d_in[5];
    const float* Se   = (const float*)d_in[6];
    const int*   nit  = (n_in >= 8) ? (const int*)d_in[7] : nullptr;
    float* out = (float*)d_out;

    int B = in_sizes[1] / 5;   // Y is (B,5)
    int nThreads = (B + PXT - 1) / PXT;

    const int TPB = 32;
    int blocks = (nThreads + TPB - 1) / TPB;
    pe_kernel<<<blocks, TPB>>>(X, Y, ch0, pf, xa, Sa, Se, nit, out, B);
}

// round 17
// speedup vs baseline: 1.0556x; 1.0556x over previous
#include <cuda_runtime.h>

#define ADAM_B1 0.9f
#define ADAM_B2 0.999f
#define ADAM_LR 0.02f
#define LOG2E_F 1.4426950408889634f
#define LN2_F   0.6931471805599453f

__device__ __forceinline__ float rcp_a(float x) {
    float r; asm("rcp.approx.f32 %0, %1;" : "=f"(r) : "f"(x)); return r;
}
__device__ __forceinline__ float rsq_a(float x) {
    float r; asm("rsqrt.approx.f32 %0, %1;" : "=f"(r) : "f"(x)); return r;
}
__device__ __forceinline__ float sqrt_a(float x) {
    float r; asm("sqrt.approx.f32 %0, %1;" : "=f"(r) : "f"(x)); return r;
}
__device__ __forceinline__ float ex2_a(float x) {
    float r; asm("ex2.approx.f32 %0, %1;" : "=f"(r) : "f"(x)); return r;
}
#define EXPA(x) ex2_a(LOG2E_F * (x))

// per-pixel state for the diag fast path (all members become registers)
struct PxState {
    float fe2[5], yfn[5];
    float cl0, cl1, cl2;
    float m0, m1, m2;
    float v0, v1, v2;
};

// ---------------- main kernel: 2 pixels per thread, PURE SCALAR, explicit state ----------------
__global__ __launch_bounds__(32)
void pe_kernel(const float* __restrict__ X,     // (B,5,5)
               const float* __restrict__ Yg,    // (B,5)
               const float* __restrict__ ch0g,  // (B,1,3)
               const float* __restrict__ pf,    // (14,)
               const float* __restrict__ xag,   // (3,)
               const float* __restrict__ Sag,   // (3,3)
               const float* __restrict__ Seg,   // (5,5)
               const int*   __restrict__ nitp,
               float* __restrict__ out,         // (B,9)
               int B)
{
    int tIdx = blockIdx.x * blockDim.x + threadIdx.x;
    int pA = 2 * tIdx;
    if (pA >= B) return;
    int pB = min(pA + 1, B - 1);

    const float L[5] = {-0.275f, 0.025f, 0.5f, 0.70f, 1.15f};

    // ---- uniform (broadcast) parameters ----
    float p0=pf[0], p1=pf[1], p2=pf[2], p3=pf[3], p4=pf[4], p5=pf[5], p6=pf[6];
    const float cna = pf[12] * 0.005f;
    const float cnb = pf[13] * 0.005f;
    const float c7s = pf[7] * 0.089f;
    const float c8s = pf[8] * 0.1245f;
    const float cnab = cna + cnb;

    float ABl[5], ACDl[5], BBSl[5];
    #pragma unroll
    for (int l = 0; l < 5; l++) {
        float aph = p0 * 0.05f * (1.0f + p1 * 0.1f * L[l] + p2 * 0.01f);
        float acd = p5 * 0.1f * expf(-p6 * 1.7f * L[l]);
        float bbs = p3 * 0.001f * (1.0f + p4 * 0.05f * L[l]);
        ABl[l]  = aph + bbs;
        ACDl[l] = acd;
        BBSl[l] = bbs;
    }

    bool diag = ((Seg[0*5+1]+Seg[1*5+0])==0.f && (Seg[0*5+2]+Seg[2*5+0])==0.f &&
                 (Seg[0*5+3]+Seg[3*5+0])==0.f && (Seg[0*5+4]+Seg[4*5+0])==0.f &&
                 (Seg[1*5+2]+Seg[2*5+1])==0.f && (Seg[1*5+3]+Seg[3*5+1])==0.f &&
                 (Seg[1*5+4]+Seg[4*5+1])==0.f && (Seg[2*5+3]+Seg[3*5+2])==0.f &&
                 (Seg[2*5+4]+Seg[4*5+2])==0.f && (Seg[3*5+4]+Seg[4*5+3])==0.f &&
                 (Sag[0*3+1]+Sag[1*3+0])==0.f && (Sag[0*3+2]+Sag[2*3+0])==0.f &&
                 (Sag[1*3+2]+Sag[2*3+1])==0.f);

    int iters = 50;
    if (nitp) {
        int it = *nitp;
        if (it >= 1 && it <= 100000000) iters = it;
        else {
            float f = __int_as_float(it);
            if (f >= 1.0f && f <= 1e8f) iters = (int)f;
        }
    }

    float b1t = 1.0f, b2t = 1.0f;
    float chla_f[2], nap_f[2], cdom_f[2], ch0_out[2];
    int px2[2] = { pA, pB };

    if (diag) {
        // ===== scalar fused diagonal path, log2-domain, explicit per-pixel state =====
        const float sa0l2 = Sag[0]*LN2_F, sa1l2 = Sag[4]*LN2_F, sa2l2 = Sag[8]*LN2_F;
        const float bp0 = -Sag[0]*xag[0], bp1 = -Sag[4]*xag[1], bp2 = -Sag[8]*xag[2];

        PxState S[2];
        #pragma unroll
        for (int s = 0; s < 2; s++) {
            int b = px2[s];
            #pragma unroll
            for (int l = 0; l < 5; l++) {
                float e0 = X[b*25 + l*5 + 0], e1 = X[b*25 + l*5 + 1];
                float fe = __fdividef(e0 + 0.5f*e1, e0 + e1);
                S[s].fe2[l] = Seg[l*5+l] * fe * fe;
                S[s].yfn[l] = -__fdividef(Yg[b*5 + l], fe);
            }
            S[s].cl0 = ch0g[b*3 + 0] * LOG2E_F;
            S[s].cl1 = ch0g[b*3 + 1] * LOG2E_F;
            S[s].cl2 = ch0g[b*3 + 2] * LOG2E_F;
            S[s].m0 = 0.f; S[s].m1 = 0.f; S[s].m2 = 0.f;
            S[s].v0 = 1e-30f; S[s].v1 = 1e-30f; S[s].v2 = 1e-30f;
        }

        #pragma unroll 2
        for (int t = 0; t < iters; t++) {
            b1t *= ADAM_B1; b2t *= ADAM_B2;
            float nlrt = (-ADAM_LR * LOG2E_F) * sqrt_a(1.0f - b2t) * rcp_a(1.0f - b1t);

            #pragma unroll
            for (int s = 0; s < 2; s++) {
                PxState& P = S[s];
                float chla = ex2_a(P.cl0);
                float nap  = ex2_a(P.cl1);
                float cdom = ex2_a(P.cl2);

                float NC = fmaf(cnab, nap, 0.0057f);
                float DB = fmaf(cnb,  nap, 0.0012f);

                float acc0, T, acc2;
                #pragma unroll
                for (int l = 0; l < 5; l++) {
                    float sv = fmaf(ABl[l], chla, fmaf(ACDl[l], cdom, NC)); // a+bb
                    float bb = fmaf(BBSl[l], chla, DB);
                    float iv = rcp_a(sv);
                    float u  = bb * iv;
                    float t1 = fmaf(c8s, u, c7s);
                    float pv = fmaf(t1, u, P.yfn[l]);        // rrs/FE - Y/FE
                    float dv = fmaf(c8s, u, t1);             // c7 + 2 c8 u
                    float q  = (P.fe2[l] * iv) * (pv * dv);
                    float qu = q * u;
                    float tg = fmaf(-u, ABl[l], BBSl[l]);    // BBS - u*(Aph+Bbs)
                    float tT = fmaf(-u, cnab, cnb);          // cnb - u*cnab
                    if (l == 0) {
                        acc0 = q * tg;
                        T    = q * tT;
                        acc2 = qu * (-ACDl[l]);
                    } else {
                        acc0 = fmaf(q, tg, acc0);
                        T    = fmaf(q, tT, T);
                        acc2 = fmaf(qu, -ACDl[l], acc2);
                    }
                }

                float g0 = fmaf(acc0, chla, fmaf(sa0l2, P.cl0, bp0));
                float g1 = fmaf(T,    nap,  fmaf(sa1l2, P.cl1, bp1));
                float g2 = fmaf(acc2, cdom, fmaf(sa2l2, P.cl2, bp2));

                // Adam, fully explicit per component
                P.m0 = fmaf(g0, 1.0f - ADAM_B1, P.m0 * ADAM_B1);
                P.v0 = fmaf(g0 * g0, 1.0f - ADAM_B2, P.v0 * ADAM_B2);
                P.cl0 = fmaf(P.m0 * rsq_a(P.v0), nlrt, P.cl0);

                P.m1 = fmaf(g1, 1.0f - ADAM_B1, P.m1 * ADAM_B1);
                P.v1 = fmaf(g1 * g1, 1.0f - ADAM_B2, P.v1 * ADAM_B2);
                P.cl1 = fmaf(P.m1 * rsq_a(P.v1), nlrt, P.cl1);

                P.m2 = fmaf(g2, 1.0f - ADAM_B1, P.m2 * ADAM_B1);
                P.v2 = fmaf(g2 * g2, 1.0f - ADAM_B2, P.v2 * ADAM_B2);
                P.cl2 = fmaf(P.m2 * rsq_a(P.v2), nlrt, P.cl2);
            }
        }
        #pragma unroll
        for (int s = 0; s < 2; s++) {
            ch0_out[s] = S[s].cl0 * LN2_F;
            chla_f[s] = ex2_a(S[s].cl0);
            nap_f[s]  = ex2_a(S[s].cl1);
            cdom_f[s] = ex2_a(S[s].cl2);
        }
    } else {
        // ===== general scalar two-pass fallback (dense Se, Sa) =====
        float Se[5][5];
        #pragma unroll
        for (int i = 0; i < 5; i++)
            #pragma unroll
            for (int j = 0; j < 5; j++)
                Se[i][j] = 0.5f * (Seg[i*5 + j] + Seg[j*5 + i]);
        float SaS[3][3];
        #pragma unroll
        for (int i = 0; i < 3; i++)
            #pragma unroll
            for (int j = 0; j < 3; j++)
                SaS[i][j] = 0.5f * (Sag[i*3 + j] + Sag[j*3 + i]);
        float xa0 = xag[0], xa1 = xag[1], xa2 = xag[2];
        float bp0 = -(SaS[0][0]*xa0 + SaS[0][1]*xa1 + SaS[0][2]*xa2);
        float bp1 = -(SaS[1][0]*xa0 + SaS[1][1]*xa1 + SaS[1][2]*xa2);
        float bp2 = -(SaS[2][0]*xa0 + SaS[2][1]*xa1 + SaS[2][2]*xa2);

        float fe[2][5], yv[2][5];
        #pragma unroll
        for (int s = 0; s < 2; s++) {
            int b = px2[s];
            #pragma unroll
            for (int l = 0; l < 5; l++) {
                float e0 = X[b*25 + l*5 + 0], e1 = X[b*25 + l*5 + 1];
                fe[s][l] = __fdividef(e0 + 0.5f*e1, e0 + e1);
                yv[s][l] = Yg[b*5 + l];
            }
        }

        float ch[2][3], m[2][3], v[2][3];
        #pragma unroll
        for (int s = 0; s < 2; s++)
            #pragma unroll
            for (int k = 0; k < 3; k++) {
                ch[s][k] = ch0g[px2[s]*3 + k];
                m[s][k] = 0.0f;
                v[s][k] = 1e-30f;
            }

        for (int t = 0; t < iters; t++) {
            b1t *= ADAM_B1; b2t *= ADAM_B2;
            float nlrt = -ADAM_LR * sqrt_a(1.0f - b2t) * rcp_a(1.0f - b1t);

            #pragma unroll
            for (int s = 0; s < 2; s++) {
                float chla = EXPA(ch[s][0]);
                float nap  = EXPA(ch[s][1]);
                float cdom = EXPA(ch[s][2]);

                float da1  = cna * nap;
                float dbb1 = cnb * nap;

                float r[5], u[5], iv[5];
                #pragma unroll
                for (int l = 0; l < 5; l++) {
                    float aph = ABl[l] - BBSl[l];
                    float a  = 0.0045f + aph*chla + ACDl[l]*cdom + da1;
                    float bb = 0.0012f + BBSl[l]*chla + dbb1;
                    iv[l] = rcp_a(a + bb);
                    u[l]  = bb * iv[l];
                    float rrs = fmaf(c8s, u[l], c7s) * u[l] * fe[s][l];
                    r[l] = rrs - yv[s][l];
                }

                float g0 = fmaf(SaS[0][0], ch[s][0], fmaf(SaS[0][1], ch[s][1], fmaf(SaS[0][2], ch[s][2], bp0)));
                float g1 = fmaf(SaS[1][0], ch[s][0], fmaf(SaS[1][1], ch[s][1], fmaf(SaS[1][2], ch[s][2], bp1)));
                float g2 = fmaf(SaS[2][0], ch[s][0], fmaf(SaS[2][1], ch[s][1], fmaf(SaS[2][2], ch[s][2], bp2)));

                #pragma unroll
                for (int l = 0; l < 5; l++) {
                    float w = fmaf(Se[l][0], r[0], fmaf(Se[l][1], r[1],
                              fmaf(Se[l][2], r[2], fmaf(Se[l][3], r[3], Se[l][4]*r[4]))));
                    float dg = fmaf(2.0f*c8s, u[l], c7s) * fe[s][l];
                    float q  = w * dg * iv[l];
                    float ul = u[l], om = 1.0f - ul;
                    float aph = ABl[l] - BBSl[l];
                    float da0 = aph*chla, dbb0 = BBSl[l]*chla;
                    float da2 = ACDl[l]*cdom;
                    g0 += q * (om * dbb0 - ul * da0);
                    g1 += q * (om * dbb1 - ul * da1);
                    g2 -= q * ul * da2;
                }

                float g[3] = { g0, g1, g2 };
                #pragma unroll
                for (int k = 0; k < 3; k++) {
                    m[s][k] = fmaf(g[k], 1.0f - ADAM_B1, m[s][k] * ADAM_B1);
                    v[s][k] = fmaf(g[k] * g[k], 1.0f - ADAM_B2, v[s][k] * ADAM_B2);
                    ch[s][k] = fmaf(m[s][k] * rsq_a(v[s][k]), nlrt, ch[s][k]);
                }
            }
        }
        #pragma unroll
        for (int s = 0; s < 2; s++) {
            ch0_out[s] = ch[s][0];
            chla_f[s] = EXPA(ch[s][0]);
            nap_f[s]  = EXPA(ch[s][1]);
            cdom_f[s] = EXPA(ch[s][2]);
        }
    }

    // ---- outputs: [ch0, kd(5), bbp(3)] — reuses loop constants ----
    {
        float kfac = pf[9] * 0.9f + pf[10] * 0.1f;
        float p11v = pf[11];
        const int J[3] = {1, 2, 4};

        #pragma unroll
        for (int s = 0; s < 2; s++) {
            int b = px2[s];
            float NCo = fmaf(cnab, nap_f[s], 0.0057f);
            float c2n = cnb * nap_f[s];

            out[b*9 + 0] = ch0_out[s];
            #pragma unroll
            for (int l = 0; l < 5; l++) {
                float ab = fmaf(ABl[l], chla_f[s], fmaf(ACDl[l], cdom_f[s], NCo));  // a+bb
                float x3 = X[b*25 + l*5 + 3];
                float mu = 0.5f + 0.5f * rcp_a(1.0f + EXPA(-x3));
                out[b*9 + 1 + l] = ab * kfac * rcp_a(mu);
            }
            #pragma unroll
            for (int j = 0; j < 3; j++) {
                out[b*9 + 6 + j] = p11v * fmaf(BBSl[J[j]], chla_f[s], c2n);
            }
        }
    }
}

extern "C" void kernel_launch(void* const* d_in, const int* in_sizes, int n_in,
                              void* d_out, int out_size) {
    const float* X    = (const float*)d_in[0];
    const float* Y    = (const float*)d_in[1];
    const float* ch0  = (const float*)d_in[2];
    const float* pf   = (const float*)d_in[3];
    const float* xa   = (const float*)d_in[4];
    const float* Sa   = (const float*)d_in[5];
    const float* Se   = (const float*)d_in[6];
    const int*   nit  = (n_in >= 8) ? (const int*)d_in[7] : nullptr;
    float* out = (float*)d_out;

    int B = in_sizes[1] / 5;   // Y is (B,5)
    int nThreads = (B + 1) / 2;

    const int TPB = 32;
    int blocks = (nThreads + TPB - 1) / TPB;
    pe_kernel<<<blocks, TPB>>>(X, Y, ch0, pf, xa, Sa, Se, nit, out, B);
}